// round 5
// baseline (speedup 1.0000x reference)
#include <cuda_runtime.h>
#include <cuda_fp16.h>
#include <cstdint>

#define KC    64            // number of selected columns
#define DCOL  1024          // columns of x
#define NTRI  2016          // upper-triangular terms
#define NM3   512
#define NM4   512
#define NM5   512
#define NMH   256           // per-CTA half of each monomial table
#define TPB   128           // threads per block
#define ROWS_PER_BLOCK 128
#define NGROUP 32           // 4-row groups (phase B)
#define NTILES 256          // 256 * 128 rows = 32768
#define NBLOCKS (NTILES*2)  // 2 CTAs per tile (term-split)
#define NROWS 32768

// -------- persistent scratch (no allocations allowed) --------
__device__ float    g_tri[NTRI];     // packed triu(b,1), row-major (i asc, j asc)
__device__ uint2    g_rec3[NM3];     // x: i0|i1<<8|i2<<16, y: c bits
__device__ uint2    g_rec4[NM4];     // x: i0..i3 packed bytes, y: c bits
__device__ uint4    g_rec5[NM5];     // x: i0..i3 bytes, y: i4, z: c bits, w: pad
__device__ float    g_a[KC];
__device__ unsigned g_xoff[KC];      // S[k]

// -------- prep kernel: pack tables + zero the output ------------------------
__global__ void prep_kernel(const float* __restrict__ b,
                            const int*   __restrict__ S,
                            const float* __restrict__ a,
                            const int*   __restrict__ idx3, const float* __restrict__ c3,
                            const int*   __restrict__ idx4, const float* __restrict__ c4,
                            const int*   __restrict__ idx5, const float* __restrict__ c5,
                            float* __restrict__ out)
{
    int t = blockIdx.x * blockDim.x + threadIdx.x;
    int nthreads = gridDim.x * blockDim.x;
    // zero output (atomicAdd accumulation target)
    for (int i = t; i < NROWS; i += nthreads) out[i] = 0.f;

    if (t < NTRI) {
        int rem = t, i = 0;
        while (rem >= 63 - i) { rem -= 63 - i; ++i; }
        int j = i + 1 + rem;
        g_tri[t] = b[i * 64 + j];
    }
    if (t < NM3) {
        unsigned p = (unsigned)idx3[t*3+0] | ((unsigned)idx3[t*3+1] << 8)
                   | ((unsigned)idx3[t*3+2] << 16);
        uint2 r; r.x = p; r.y = __float_as_uint(c3[t]);
        g_rec3[t] = r;
    }
    if (t < NM4) {
        unsigned p = (unsigned)idx4[t*4+0] | ((unsigned)idx4[t*4+1] << 8)
                   | ((unsigned)idx4[t*4+2] << 16) | ((unsigned)idx4[t*4+3] << 24);
        uint2 r; r.x = p; r.y = __float_as_uint(c4[t]);
        g_rec4[t] = r;
    }
    if (t < NM5) {
        unsigned p = (unsigned)idx5[t*5+0] | ((unsigned)idx5[t*5+1] << 8)
                   | ((unsigned)idx5[t*5+2] << 16) | ((unsigned)idx5[t*5+3] << 24);
        uint4 r; r.x = p; r.y = (unsigned)idx5[t*5+4];
        r.z = __float_as_uint(c5[t]); r.w = 0u;
        g_rec5[t] = r;
    }
    if (t < KC) {
        g_a[t]    = a[t];
        g_xoff[t] = (unsigned)S[t];
    }
}

__device__ __forceinline__ __half2 as_h2(unsigned u) {
    __half2 h;
    *reinterpret_cast<unsigned*>(&h) = u;
    return h;
}

// -------- main kernel: 2 CTAs per 128-row tile, monomial terms split --------
__global__ __launch_bounds__(TPB)
void poly_kernel(const float* __restrict__ x, float* __restrict__ out)
{
    __shared__ float    s_tri[NTRI];               // 8064 B (used by parity 0 only)
    __shared__ uint2    s_rec3[NMH];               // 2 KB (this CTA's half)
    __shared__ uint2    s_rec4[NMH];               // 2 KB
    __shared__ uint4    s_rec5[NMH];               // 4 KB
    __shared__ float    s_a[KC];
    __shared__ unsigned s_xi[KC];
    __shared__ __half   s_x[KC][ROWS_PER_BLOCK];   // 16 KB, row stride 256B
    __shared__ float    s_acc[ROWS_PER_BLOCK];     // per-row lin+quad (parity 0)
    __shared__ float    s_redf[4][ROWS_PER_BLOCK]; // monomial partials

    const int tid  = threadIdx.x;
    const int tile = blockIdx.x >> 1;
    const int par  = blockIdx.x & 1;
    const int base = par * NMH;

    // cooperative preload: own half of each monomial table (+ tri for parity 0)
    {
        if (par == 0) {
            const float4* ts = (const float4*)g_tri;
            float4*       td = (float4*)s_tri;
            #pragma unroll 1
            for (int i = tid; i < NTRI/4; i += TPB) td[i] = ts[i];
        }
        #pragma unroll 1
        for (int i = tid; i < NMH; i += TPB) s_rec3[i] = g_rec3[base + i];
        #pragma unroll 1
        for (int i = tid; i < NMH; i += TPB) s_rec4[i] = g_rec4[base + i];
        #pragma unroll 1
        for (int i = tid; i < NMH; i += TPB) s_rec5[i] = g_rec5[base + i];
        if (tid < KC) { s_a[tid] = g_a[tid]; s_xi[tid] = g_xoff[tid]; }
    }
    __syncthreads();

    // ---------------- phase A: gather (+ quad/lin on parity 0) ---------------
    {
        const long long row = (long long)tile * ROWS_PER_BLOCK + tid;
        const float* xr = x + row * DCOL;
        float xv[KC];
        #pragma unroll
        for (int k = 0; k < KC; ++k) xv[k] = __ldg(xr + s_xi[k]);

        // publish fp16 copy for the monomial phase
        #pragma unroll
        for (int k = 0; k < KC; ++k)
            s_x[k][tid] = __float2half(xv[k]);

        float a0 = 0.f;
        if (par == 0) {
            #pragma unroll
            for (int k = 0; k < KC; ++k) a0 = fmaf(s_a[k], xv[k], a0);

            const float4* tri4 = (const float4*)s_tri;
            float4 tb = make_float4(0.f, 0.f, 0.f, 0.f);
            int p = 0;
            #pragma unroll
            for (int i = 0; i < KC - 1; ++i) {
                float s = 0.f;
                #pragma unroll
                for (int j = i + 1; j < KC; ++j) {
                    if ((p & 3) == 0) tb = tri4[p >> 2];
                    float bv = ((p & 3) == 0) ? tb.x :
                               ((p & 3) == 1) ? tb.y :
                               ((p & 3) == 2) ? tb.z : tb.w;
                    s = fmaf(bv, xv[j], s);
                    ++p;
                }
                a0 = fmaf(s, xv[i], a0);
            }
        }
        s_acc[tid] = a0;   // 0 for parity 1
    }
    __syncthreads();

    // ---------------- phase B: monomials on 4-row groups, half the terms -----
    const int g = tid & (NGROUP - 1);   // group id 0..31 (rows 4g..4g+3)
    const int q = tid >> 5;             // term quarter 0..3 (warp-uniform)
    const char* xb = (const char*)(&s_x[0][0]) + 8 * g;  // operand offset = idx<<8
    float m0 = 0.f, m1 = 0.f, m2 = 0.f, m3 = 0.f;

    {
        const int lo = q * (NMH / 4), hi = lo + (NMH / 4);
        #pragma unroll 4
        for (int t3 = lo; t3 < hi; ++t3) {
            uint2 r = s_rec3[t3];
            unsigned o0 = (r.x << 8) & 0xFF00u;
            unsigned o1 =  r.x       & 0xFF00u;
            unsigned o2 = (r.x >> 8) & 0xFF00u;
            uint2 u0 = *(const uint2*)(xb + o0);
            uint2 u1 = *(const uint2*)(xb + o1);
            uint2 u2 = *(const uint2*)(xb + o2);
            __half2 pa = __hmul2(__hmul2(as_h2(u0.x), as_h2(u1.x)), as_h2(u2.x));
            __half2 pb = __hmul2(__hmul2(as_h2(u0.y), as_h2(u1.y)), as_h2(u2.y));
            float2 fa = __half22float2(pa);
            float2 fb = __half22float2(pb);
            float c = __uint_as_float(r.y);
            m0 = fmaf(c, fa.x, m0);
            m1 = fmaf(c, fa.y, m1);
            m2 = fmaf(c, fb.x, m2);
            m3 = fmaf(c, fb.y, m3);
        }
    }
    {
        const int lo = q * (NMH / 4), hi = lo + (NMH / 4);
        #pragma unroll 4
        for (int t4 = lo; t4 < hi; ++t4) {
            uint2 r = s_rec4[t4];
            unsigned o0 = (r.x << 8)  & 0xFF00u;
            unsigned o1 =  r.x        & 0xFF00u;
            unsigned o2 = (r.x >> 8)  & 0xFF00u;
            unsigned o3 = (r.x >> 16) & 0xFF00u;
            uint2 u0 = *(const uint2*)(xb + o0);
            uint2 u1 = *(const uint2*)(xb + o1);
            uint2 u2 = *(const uint2*)(xb + o2);
            uint2 u3 = *(const uint2*)(xb + o3);
            __half2 pa = __hmul2(__hmul2(as_h2(u0.x), as_h2(u1.x)),
                                 __hmul2(as_h2(u2.x), as_h2(u3.x)));
            __half2 pb = __hmul2(__hmul2(as_h2(u0.y), as_h2(u1.y)),
                                 __hmul2(as_h2(u2.y), as_h2(u3.y)));
            float2 fa = __half22float2(pa);
            float2 fb = __half22float2(pb);
            float c = __uint_as_float(r.y);
            m0 = fmaf(c, fa.x, m0);
            m1 = fmaf(c, fa.y, m1);
            m2 = fmaf(c, fb.x, m2);
            m3 = fmaf(c, fb.y, m3);
        }
    }
    {
        const int lo = q * (NMH / 4), hi = lo + (NMH / 4);
        #pragma unroll 4
        for (int t5 = lo; t5 < hi; ++t5) {
            uint4 r = s_rec5[t5];
            unsigned o0 = (r.x << 8)  & 0xFF00u;
            unsigned o1 =  r.x        & 0xFF00u;
            unsigned o2 = (r.x >> 8)  & 0xFF00u;
            unsigned o3 = (r.x >> 16) & 0xFF00u;
            unsigned o4 =  r.y << 8;
            uint2 u0 = *(const uint2*)(xb + o0);
            uint2 u1 = *(const uint2*)(xb + o1);
            uint2 u2 = *(const uint2*)(xb + o2);
            uint2 u3 = *(const uint2*)(xb + o3);
            uint2 u4 = *(const uint2*)(xb + o4);
            __half2 pa = __hmul2(__hmul2(__hmul2(as_h2(u0.x), as_h2(u1.x)),
                                         __hmul2(as_h2(u2.x), as_h2(u3.x))),
                                 as_h2(u4.x));
            __half2 pb = __hmul2(__hmul2(__hmul2(as_h2(u0.y), as_h2(u1.y)),
                                         __hmul2(as_h2(u2.y), as_h2(u3.y))),
                                 as_h2(u4.y));
            float2 fa = __half22float2(pa);
            float2 fb = __half22float2(pb);
            float c = __uint_as_float(r.z);
            m0 = fmaf(c, fa.x, m0);
            m1 = fmaf(c, fa.y, m1);
            m2 = fmaf(c, fb.x, m2);
            m3 = fmaf(c, fb.y, m3);
        }
    }

    *(float4*)&s_redf[q][4 * g] = make_float4(m0, m1, m2, m3);
    __syncthreads();

    // one thread per row: combine this CTA's contribution, accumulate to out
    {
        float r = s_acc[tid]
                + s_redf[0][tid] + s_redf[1][tid]
                + s_redf[2][tid] + s_redf[3][tid];
        atomicAdd(out + (long long)tile * ROWS_PER_BLOCK + tid, r);
    }
}

// -------- launch --------
extern "C" void kernel_launch(void* const* d_in, const int* in_sizes, int n_in,
                              void* d_out, int out_size)
{
    const float* x    = (const float*)d_in[0];
    const int*   S    = (const int*)  d_in[1];
    const float* a    = (const float*)d_in[2];
    const float* b    = (const float*)d_in[3];
    const int*   idx3 = (const int*)  d_in[4];
    const float* c3   = (const float*)d_in[5];
    const int*   idx4 = (const int*)  d_in[6];
    const float* c4   = (const float*)d_in[7];
    const int*   idx5 = (const int*)  d_in[8];
    const float* c5   = (const float*)d_in[9];
    float* out = (float*)d_out;

    prep_kernel<<<8, 256>>>(b, S, a, idx3, c3, idx4, c4, idx5, c5, out);
    poly_kernel<<<NBLOCKS, TPB>>>(x, out);
}

// round 6
// speedup vs baseline: 1.1176x; 1.1176x over previous
#include <cuda_runtime.h>
#include <cuda_fp16.h>
#include <cstdint>

#define KC    64            // number of selected columns
#define DCOL  1024          // columns of x
#define NTRI  2016          // upper-triangular terms
#define NM3   512
#define NM4   512
#define NM5   512
#define TPB   128           // threads per block
#define ROWS  64            // rows per block
#define NGROUP 16           // 4-row groups (phase B)
#define NSLICE 8            // term slices (phase B)
#define NBLOCKS 512         // 512 * 64 rows = 32768

// -------- persistent scratch (no allocations allowed) --------
__device__ float    g_tri[NTRI];     // packed triu(b,1), row-major (i asc, j asc)
__device__ uint2    g_rec3[NM3];     // x: i0|i1<<8|i2<<16, y: c bits
__device__ uint2    g_rec4[NM4];     // x: i0..i3 packed bytes, y: c bits
__device__ uint4    g_rec5[NM5];     // x: i0..i3 bytes, y: i4, z: c bits, w: pad
__device__ float    g_a[KC];
__device__ unsigned g_xoff[KC];      // S[k]

// -------- prep kernel --------
__global__ void prep_kernel(const float* __restrict__ b,
                            const int*   __restrict__ S,
                            const float* __restrict__ a,
                            const int*   __restrict__ idx3, const float* __restrict__ c3,
                            const int*   __restrict__ idx4, const float* __restrict__ c4,
                            const int*   __restrict__ idx5, const float* __restrict__ c5)
{
    int t = blockIdx.x * blockDim.x + threadIdx.x;
    if (t < NTRI) {
        int rem = t, i = 0;
        while (rem >= 63 - i) { rem -= 63 - i; ++i; }
        int j = i + 1 + rem;
        g_tri[t] = b[i * 64 + j];
    }
    if (t < NM3) {
        unsigned p = (unsigned)idx3[t*3+0] | ((unsigned)idx3[t*3+1] << 8)
                   | ((unsigned)idx3[t*3+2] << 16);
        uint2 r; r.x = p; r.y = __float_as_uint(c3[t]);
        g_rec3[t] = r;
    }
    if (t < NM4) {
        unsigned p = (unsigned)idx4[t*4+0] | ((unsigned)idx4[t*4+1] << 8)
                   | ((unsigned)idx4[t*4+2] << 16) | ((unsigned)idx4[t*4+3] << 24);
        uint2 r; r.x = p; r.y = __float_as_uint(c4[t]);
        g_rec4[t] = r;
    }
    if (t < NM5) {
        unsigned p = (unsigned)idx5[t*5+0] | ((unsigned)idx5[t*5+1] << 8)
                   | ((unsigned)idx5[t*5+2] << 16) | ((unsigned)idx5[t*5+3] << 24);
        uint4 r; r.x = p; r.y = (unsigned)idx5[t*5+4];
        r.z = __float_as_uint(c5[t]); r.w = 0u;
        g_rec5[t] = r;
    }
    if (t < KC) {
        g_a[t]    = a[t];
        g_xoff[t] = (unsigned)S[t];
    }
}

__device__ __forceinline__ __half2 as_h2(unsigned u) {
    __half2 h;
    *reinterpret_cast<unsigned*>(&h) = u;
    return h;
}

// -------- main kernel: 64-row tiles, warp-specialized preload, -------------
// -------- 4-row-group / 8-slice monomial phase ------------------------------
__global__ __launch_bounds__(TPB)
void poly_kernel(const float* __restrict__ x, float* __restrict__ out)
{
    __shared__ float    s_tri[NTRI];            // 8064 B
    __shared__ uint2    s_rec3[NM3];            // 4 KB
    __shared__ uint2    s_rec4[NM4];            // 4 KB
    __shared__ uint4    s_rec5[NM5];            // 8 KB
    __shared__ float    s_a[KC];
    __shared__ unsigned s_xi[KC];
    __shared__ __half   s_x[KC][ROWS];          // [64][64] half = 8 KB, row stride 128B
    __shared__ float    s_acc[ROWS];            // per-row lin+quad
    __shared__ float    s_redf[NSLICE][ROWS];   // 2 KB monomial partials

    const int tid = threadIdx.x;

    // split preload: warps 0-1 stage a/S, warps 2-3 stream the big tables
    if (tid < 64) {
        s_a[tid]  = g_a[tid];
        s_xi[tid] = g_xoff[tid];
    } else {
        const int t = tid - 64;   // 0..63
        const float4* ts = (const float4*)g_tri;
        float4*       td = (float4*)s_tri;
        #pragma unroll 1
        for (int i = t; i < NTRI/4; i += 64) td[i] = ts[i];
        #pragma unroll 1
        for (int i = t; i < NM3; i += 64) s_rec3[i] = g_rec3[i];
        #pragma unroll 1
        for (int i = t; i < NM4; i += 64) s_rec4[i] = g_rec4[i];
        #pragma unroll 1
        for (int i = t; i < NM5; i += 64) s_rec5[i] = g_rec5[i];
    }
    __syncthreads();

    // ---------------- phase A: warps 0-1 gather + quad; warps 2-3 wait ------
    if (tid < ROWS) {
        const long long row = (long long)blockIdx.x * ROWS + tid;
        const float* xr = x + row * DCOL;
        float xv[KC];
        #pragma unroll
        for (int k = 0; k < KC; ++k) xv[k] = __ldg(xr + s_xi[k]);

        // publish fp16 copy for the monomial phase
        #pragma unroll
        for (int k = 0; k < KC; ++k)
            s_x[k][tid] = __float2half(xv[k]);

        float a0 = 0.f;
        #pragma unroll
        for (int k = 0; k < KC; ++k) a0 = fmaf(s_a[k], xv[k], a0);

        // quadratic form: fully unrolled triangular loop, x in registers,
        // packed-tri coefficients via broadcast LDS.128
        {
            const float4* tri4 = (const float4*)s_tri;
            float4 tb = make_float4(0.f, 0.f, 0.f, 0.f);
            int p = 0;
            #pragma unroll
            for (int i = 0; i < KC - 1; ++i) {
                float s = 0.f;
                #pragma unroll
                for (int j = i + 1; j < KC; ++j) {
                    if ((p & 3) == 0) tb = tri4[p >> 2];
                    float bv = ((p & 3) == 0) ? tb.x :
                               ((p & 3) == 1) ? tb.y :
                               ((p & 3) == 2) ? tb.z : tb.w;
                    s = fmaf(bv, xv[j], s);
                    ++p;
                }
                a0 = fmaf(s, xv[i], a0);
            }
        }
        s_acc[tid] = a0;
    }
    __syncthreads();

    // ---------------- phase B: monomials on 4-row groups, 8 slices ----------
    // group g covers rows 4g..4g+3; one LDS.64 fetches an operand for all 4.
    const int g = tid & (NGROUP - 1);   // group id 0..15
    const int q = tid >> 4;             // term slice 0..7
    const char* xb = (const char*)(&s_x[0][0]) + 8 * g;  // operand offset = idx<<7
    float m0 = 0.f, m1 = 0.f, m2 = 0.f, m3 = 0.f;

    {
        const int lo = q * (NM3 / NSLICE), hi = lo + (NM3 / NSLICE);
        #pragma unroll 4
        for (int t3 = lo; t3 < hi; ++t3) {
            uint2 r = s_rec3[t3];
            unsigned o0 = (r.x << 7) & 0x3F80u;
            unsigned o1 = (r.x >> 1) & 0x3F80u;
            unsigned o2 = (r.x >> 9) & 0x3F80u;
            uint2 u0 = *(const uint2*)(xb + o0);
            uint2 u1 = *(const uint2*)(xb + o1);
            uint2 u2 = *(const uint2*)(xb + o2);
            __half2 pa = __hmul2(__hmul2(as_h2(u0.x), as_h2(u1.x)), as_h2(u2.x));
            __half2 pb = __hmul2(__hmul2(as_h2(u0.y), as_h2(u1.y)), as_h2(u2.y));
            float2 fa = __half22float2(pa);
            float2 fb = __half22float2(pb);
            float c = __uint_as_float(r.y);
            m0 = fmaf(c, fa.x, m0);
            m1 = fmaf(c, fa.y, m1);
            m2 = fmaf(c, fb.x, m2);
            m3 = fmaf(c, fb.y, m3);
        }
    }
    {
        const int lo = q * (NM4 / NSLICE), hi = lo + (NM4 / NSLICE);
        #pragma unroll 4
        for (int t4 = lo; t4 < hi; ++t4) {
            uint2 r = s_rec4[t4];
            unsigned o0 = (r.x << 7)  & 0x3F80u;
            unsigned o1 = (r.x >> 1)  & 0x3F80u;
            unsigned o2 = (r.x >> 9)  & 0x3F80u;
            unsigned o3 = (r.x >> 17) & 0x3F80u;
            uint2 u0 = *(const uint2*)(xb + o0);
            uint2 u1 = *(const uint2*)(xb + o1);
            uint2 u2 = *(const uint2*)(xb + o2);
            uint2 u3 = *(const uint2*)(xb + o3);
            __half2 pa = __hmul2(__hmul2(as_h2(u0.x), as_h2(u1.x)),
                                 __hmul2(as_h2(u2.x), as_h2(u3.x)));
            __half2 pb = __hmul2(__hmul2(as_h2(u0.y), as_h2(u1.y)),
                                 __hmul2(as_h2(u2.y), as_h2(u3.y)));
            float2 fa = __half22float2(pa);
            float2 fb = __half22float2(pb);
            float c = __uint_as_float(r.y);
            m0 = fmaf(c, fa.x, m0);
            m1 = fmaf(c, fa.y, m1);
            m2 = fmaf(c, fb.x, m2);
            m3 = fmaf(c, fb.y, m3);
        }
    }
    {
        const int lo = q * (NM5 / NSLICE), hi = lo + (NM5 / NSLICE);
        #pragma unroll 4
        for (int t5 = lo; t5 < hi; ++t5) {
            uint4 r = s_rec5[t5];
            unsigned o0 = (r.x << 7)  & 0x3F80u;
            unsigned o1 = (r.x >> 1)  & 0x3F80u;
            unsigned o2 = (r.x >> 9)  & 0x3F80u;
            unsigned o3 = (r.x >> 17) & 0x3F80u;
            unsigned o4 =  r.y << 7;
            uint2 u0 = *(const uint2*)(xb + o0);
            uint2 u1 = *(const uint2*)(xb + o1);
            uint2 u2 = *(const uint2*)(xb + o2);
            uint2 u3 = *(const uint2*)(xb + o3);
            uint2 u4 = *(const uint2*)(xb + o4);
            __half2 pa = __hmul2(__hmul2(__hmul2(as_h2(u0.x), as_h2(u1.x)),
                                         __hmul2(as_h2(u2.x), as_h2(u3.x))),
                                 as_h2(u4.x));
            __half2 pb = __hmul2(__hmul2(__hmul2(as_h2(u0.y), as_h2(u1.y)),
                                         __hmul2(as_h2(u2.y), as_h2(u3.y))),
                                 as_h2(u4.y));
            float2 fa = __half22float2(pa);
            float2 fb = __half22float2(pb);
            float c = __uint_as_float(r.z);
            m0 = fmaf(c, fa.x, m0);
            m1 = fmaf(c, fa.y, m1);
            m2 = fmaf(c, fb.x, m2);
            m3 = fmaf(c, fb.y, m3);
        }
    }

    // s_redf[q][4g..4g+3] = partials for the 4 rows of group g
    *(float4*)&s_redf[q][4 * g] = make_float4(m0, m1, m2, m3);
    __syncthreads();

    // one thread per row combines quad + 8 monomial slices
    if (tid < ROWS) {
        float r = s_acc[tid];
        #pragma unroll
        for (int s = 0; s < NSLICE; ++s) r += s_redf[s][tid];
        out[blockIdx.x * ROWS + tid] = r;
    }
}

// -------- launch --------
extern "C" void kernel_launch(void* const* d_in, const int* in_sizes, int n_in,
                              void* d_out, int out_size)
{
    const float* x    = (const float*)d_in[0];
    const int*   S    = (const int*)  d_in[1];
    const float* a    = (const float*)d_in[2];
    const float* b    = (const float*)d_in[3];
    const int*   idx3 = (const int*)  d_in[4];
    const float* c3   = (const float*)d_in[5];
    const int*   idx4 = (const int*)  d_in[6];
    const float* c4   = (const float*)d_in[7];
    const int*   idx5 = (const int*)  d_in[8];
    const float* c5   = (const float*)d_in[9];
    float* out = (float*)d_out;

    prep_kernel<<<8, 256>>>(b, S, a, idx3, c3, idx4, c4, idx5, c5);
    poly_kernel<<<NBLOCKS, TPB>>>(x, out);
}

// round 7
// speedup vs baseline: 1.2313x; 1.1018x over previous
#include <cuda_runtime.h>
#include <cuda_fp16.h>
#include <cstdint>

#define KC    64            // number of selected columns
#define DCOL  1024          // columns of x
#define NTRI  2016          // upper-triangular terms
#define NM3   512
#define NM4   512
#define NM5   512
#define TPB   128
#define TROWS 128           // rows per tile
#define NTILES 256          // 256 * 128 = 32768 rows
#define NROWS 32768
#define NMH   256           // terms of each table per mono-CTA (half)

// -------- persistent scratch (no allocations allowed) --------
__device__ float    g_tri[NTRI];     // packed triu(b,1), row-major (i asc, j asc)
__device__ uint2    g_rec3[NM3];     // x: i0|i1<<8|i2<<16, y: c bits
__device__ uint2    g_rec4[NM4];     // x: i0..i3 packed bytes, y: c bits
__device__ uint4    g_rec5[NM5];     // x: i0..i3 bytes, y: i4, z: c bits, w: pad
__device__ float    g_a[KC];
__device__ unsigned g_xoff[KC];      // S[k]
__device__ __half   g_xs[NTILES * KC * TROWS];  // 4 MB fp16 gathered tiles [tile][col][row]

// -------- prep kernel --------
__global__ void prep_kernel(const float* __restrict__ b,
                            const int*   __restrict__ S,
                            const float* __restrict__ a,
                            const int*   __restrict__ idx3, const float* __restrict__ c3,
                            const int*   __restrict__ idx4, const float* __restrict__ c4,
                            const int*   __restrict__ idx5, const float* __restrict__ c5)
{
    int t = blockIdx.x * blockDim.x + threadIdx.x;
    if (t < NTRI) {
        int rem = t, i = 0;
        while (rem >= 63 - i) { rem -= 63 - i; ++i; }
        int j = i + 1 + rem;
        g_tri[t] = b[i * 64 + j];
    }
    if (t < NM3) {
        unsigned p = (unsigned)idx3[t*3+0] | ((unsigned)idx3[t*3+1] << 8)
                   | ((unsigned)idx3[t*3+2] << 16);
        uint2 r; r.x = p; r.y = __float_as_uint(c3[t]);
        g_rec3[t] = r;
    }
    if (t < NM4) {
        unsigned p = (unsigned)idx4[t*4+0] | ((unsigned)idx4[t*4+1] << 8)
                   | ((unsigned)idx4[t*4+2] << 16) | ((unsigned)idx4[t*4+3] << 24);
        uint2 r; r.x = p; r.y = __float_as_uint(c4[t]);
        g_rec4[t] = r;
    }
    if (t < NM5) {
        unsigned p = (unsigned)idx5[t*5+0] | ((unsigned)idx5[t*5+1] << 8)
                   | ((unsigned)idx5[t*5+2] << 16) | ((unsigned)idx5[t*5+3] << 24);
        uint4 r; r.x = p; r.y = (unsigned)idx5[t*5+4];
        r.z = __float_as_uint(c5[t]); r.w = 0u;
        g_rec5[t] = r;
    }
    if (t < KC) {
        g_a[t]    = a[t];
        g_xoff[t] = (unsigned)S[t];
    }
}

// -------- kernel 1: gather + linear + quadratic; spill fp16 tile ------------
__global__ __launch_bounds__(TPB)
void quad_kernel(const float* __restrict__ x, float* __restrict__ out)
{
    __shared__ float    s_tri[NTRI];     // 8064 B
    __shared__ float    s_a[KC];
    __shared__ unsigned s_xi[KC];

    const int tid = threadIdx.x;

    {
        const float4* ts = (const float4*)g_tri;
        float4*       td = (float4*)s_tri;
        #pragma unroll 1
        for (int i = tid; i < NTRI/4; i += TPB) td[i] = ts[i];
        if (tid < KC) { s_a[tid] = g_a[tid]; s_xi[tid] = g_xoff[tid]; }
    }
    __syncthreads();

    const long long row = (long long)blockIdx.x * TPB + tid;
    const float* xr = x + row * DCOL;
    float xv[KC];
    #pragma unroll
    for (int k = 0; k < KC; ++k) xv[k] = __ldg(xr + s_xi[k]);

    // spill fp16 tile: [tile=blockIdx.x][col k][row tid], coalesced 2B stores
    {
        __half* xt = g_xs + (size_t)blockIdx.x * (KC * TROWS);
        #pragma unroll
        for (int k = 0; k < KC; ++k) xt[k * TROWS + tid] = __float2half(xv[k]);
    }

    float a0 = 0.f;
    #pragma unroll
    for (int k = 0; k < KC; ++k) a0 = fmaf(s_a[k], xv[k], a0);

    // quadratic form: fully unrolled triangular loop, broadcast LDS.128 coeffs
    {
        const float4* tri4 = (const float4*)s_tri;
        float4 tb = make_float4(0.f, 0.f, 0.f, 0.f);
        int p = 0;
        #pragma unroll
        for (int i = 0; i < KC - 1; ++i) {
            float s = 0.f;
            #pragma unroll
            for (int j = i + 1; j < KC; ++j) {
                if ((p & 3) == 0) tb = tri4[p >> 2];
                float bv = ((p & 3) == 0) ? tb.x :
                           ((p & 3) == 1) ? tb.y :
                           ((p & 3) == 2) ? tb.z : tb.w;
                s = fmaf(bv, xv[j], s);
                ++p;
            }
            a0 = fmaf(s, xv[i], a0);
        }
    }
    out[row] = a0;
}

__device__ __forceinline__ __half2 as_h2(unsigned u) {
    __half2 h;
    *reinterpret_cast<unsigned*>(&h) = u;
    return h;
}

// -------- kernel 2: monomials; 2 CTAs per tile (term halves) ----------------
__global__ __launch_bounds__(TPB)
void mono_kernel(float* __restrict__ out)
{
    __shared__ __half s_x[KC][TROWS];    // 16 KB, row stride 256B
    __shared__ float  s_redf[4][TROWS];  // 2 KB

    const int tid  = threadIdx.x;
    const int tile = blockIdx.x >> 1;
    const int par  = blockIdx.x & 1;

    // coalesced tile load: 16 KB = 1024 uint4 (L2-resident, just written)
    {
        const uint4* src = (const uint4*)(g_xs + (size_t)tile * (KC * TROWS));
        uint4*       dst = (uint4*)&s_x[0][0];
        #pragma unroll
        for (int i = 0; i < 8; ++i) dst[tid + i * TPB] = __ldg(src + tid + i * TPB);
    }
    __syncthreads();

    // 32 four-row groups x 4 warp slices (conflict-free LDS.64, R4 geometry)
    const int g = tid & 31;             // group id: rows 4g..4g+3
    const int q = tid >> 5;             // warp slice 0..3
    const char* xb = (const char*)(&s_x[0][0]) + 8 * g;  // operand offset = idx<<8
    const int base = par * NMH;         // this CTA's term half
    float m0 = 0.f, m1 = 0.f, m2 = 0.f, m3 = 0.f;

    {
        const int lo = base + q * (NMH / 4), hi = lo + (NMH / 4);
        #pragma unroll 4
        for (int t3 = lo; t3 < hi; ++t3) {
            uint2 r = __ldg(&g_rec3[t3]);
            unsigned o0 = (r.x << 8) & 0xFF00u;
            unsigned o1 =  r.x       & 0xFF00u;
            unsigned o2 = (r.x >> 8) & 0xFF00u;
            uint2 u0 = *(const uint2*)(xb + o0);
            uint2 u1 = *(const uint2*)(xb + o1);
            uint2 u2 = *(const uint2*)(xb + o2);
            __half2 pa = __hmul2(__hmul2(as_h2(u0.x), as_h2(u1.x)), as_h2(u2.x));
            __half2 pb = __hmul2(__hmul2(as_h2(u0.y), as_h2(u1.y)), as_h2(u2.y));
            float2 fa = __half22float2(pa);
            float2 fb = __half22float2(pb);
            float c = __uint_as_float(r.y);
            m0 = fmaf(c, fa.x, m0);
            m1 = fmaf(c, fa.y, m1);
            m2 = fmaf(c, fb.x, m2);
            m3 = fmaf(c, fb.y, m3);
        }
    }
    {
        const int lo = base + q * (NMH / 4), hi = lo + (NMH / 4);
        #pragma unroll 4
        for (int t4 = lo; t4 < hi; ++t4) {
            uint2 r = __ldg(&g_rec4[t4]);
            unsigned o0 = (r.x << 8)  & 0xFF00u;
            unsigned o1 =  r.x        & 0xFF00u;
            unsigned o2 = (r.x >> 8)  & 0xFF00u;
            unsigned o3 = (r.x >> 16) & 0xFF00u;
            uint2 u0 = *(const uint2*)(xb + o0);
            uint2 u1 = *(const uint2*)(xb + o1);
            uint2 u2 = *(const uint2*)(xb + o2);
            uint2 u3 = *(const uint2*)(xb + o3);
            __half2 pa = __hmul2(__hmul2(as_h2(u0.x), as_h2(u1.x)),
                                 __hmul2(as_h2(u2.x), as_h2(u3.x)));
            __half2 pb = __hmul2(__hmul2(as_h2(u0.y), as_h2(u1.y)),
                                 __hmul2(as_h2(u2.y), as_h2(u3.y)));
            float2 fa = __half22float2(pa);
            float2 fb = __half22float2(pb);
            float c = __uint_as_float(r.y);
            m0 = fmaf(c, fa.x, m0);
            m1 = fmaf(c, fa.y, m1);
            m2 = fmaf(c, fb.x, m2);
            m3 = fmaf(c, fb.y, m3);
        }
    }
    {
        const int lo = base + q * (NMH / 4), hi = lo + (NMH / 4);
        #pragma unroll 4
        for (int t5 = lo; t5 < hi; ++t5) {
            uint4 r = __ldg(&g_rec5[t5]);
            unsigned o0 = (r.x << 8)  & 0xFF00u;
            unsigned o1 =  r.x        & 0xFF00u;
            unsigned o2 = (r.x >> 8)  & 0xFF00u;
            unsigned o3 = (r.x >> 16) & 0xFF00u;
            unsigned o4 =  r.y << 8;
            uint2 u0 = *(const uint2*)(xb + o0);
            uint2 u1 = *(const uint2*)(xb + o1);
            uint2 u2 = *(const uint2*)(xb + o2);
            uint2 u3 = *(const uint2*)(xb + o3);
            uint2 u4 = *(const uint2*)(xb + o4);
            __half2 pa = __hmul2(__hmul2(__hmul2(as_h2(u0.x), as_h2(u1.x)),
                                         __hmul2(as_h2(u2.x), as_h2(u3.x))),
                                 as_h2(u4.x));
            __half2 pb = __hmul2(__hmul2(__hmul2(as_h2(u0.y), as_h2(u1.y)),
                                         __hmul2(as_h2(u2.y), as_h2(u3.y))),
                                 as_h2(u4.y));
            float2 fa = __half22float2(pa);
            float2 fb = __half22float2(pb);
            float c = __uint_as_float(r.z);
            m0 = fmaf(c, fa.x, m0);
            m1 = fmaf(c, fa.y, m1);
            m2 = fmaf(c, fb.x, m2);
            m3 = fmaf(c, fb.y, m3);
        }
    }

    *(float4*)&s_redf[q][4 * g] = make_float4(m0, m1, m2, m3);
    __syncthreads();

    // one thread per row: combine this CTA's 4 slices, accumulate to out
    {
        float r = s_redf[0][tid] + s_redf[1][tid] + s_redf[2][tid] + s_redf[3][tid];
        atomicAdd(out + (size_t)tile * TROWS + tid, r);
    }
}

// -------- launch --------
extern "C" void kernel_launch(void* const* d_in, const int* in_sizes, int n_in,
                              void* d_out, int out_size)
{
    const float* x    = (const float*)d_in[0];
    const int*   S    = (const int*)  d_in[1];
    const float* a    = (const float*)d_in[2];
    const float* b    = (const float*)d_in[3];
    const int*   idx3 = (const int*)  d_in[4];
    const float* c3   = (const float*)d_in[5];
    const int*   idx4 = (const int*)  d_in[6];
    const float* c4   = (const float*)d_in[7];
    const int*   idx5 = (const int*)  d_in[8];
    const float* c5   = (const float*)d_in[9];
    float* out = (float*)d_out;

    prep_kernel<<<8, 256>>>(b, S, a, idx3, c3, idx4, c4, idx5, c5);
    quad_kernel<<<NTILES, TPB>>>(x, out);          // writes out = lin+quad, spills fp16 tiles
    mono_kernel<<<NTILES * 2, TPB>>>(out);         // += monomials (2 halves per tile)
}

// round 8
// speedup vs baseline: 1.2746x; 1.0351x over previous
#include <cuda_runtime.h>
#include <cuda_fp16.h>
#include <cstdint>

#define KC    64            // number of selected columns
#define DCOL  1024          // columns of x
#define NTRI  2016          // upper-triangular terms
#define NM3   512
#define NM4   512
#define NM5   512
#define TPB   128
#define TROWS 128           // rows per tile
#define NTILES 256          // 256 * 128 = 32768 rows
#define NROWS 32768
#define NSPLIT 4            // mono CTAs per tile (term quarters)
#define NMQ   (NM3/NSPLIT)  // 128 terms of each table per mono-CTA

// -------- persistent scratch (no allocations allowed) --------
__device__ float    g_tri[NTRI];     // packed triu(b,1), row-major (i asc, j asc)
__device__ uint2    g_rec3[NM3];     // x: i0|i1<<8|i2<<16, y: c bits
__device__ uint2    g_rec4[NM4];     // x: i0..i3 packed bytes, y: c bits
__device__ uint4    g_rec5[NM5];     // x: i0..i3 bytes, y: i4, z: c bits, w: pad
__device__ float    g_a[KC];
__device__ unsigned g_xoff[KC];      // S[k]
__device__ __half   g_xs[NTILES * KC * TROWS];  // 4 MB fp16 gathered tiles [tile][col][row]

// -------- prep kernel --------
__global__ void prep_kernel(const float* __restrict__ b,
                            const int*   __restrict__ S,
                            const float* __restrict__ a,
                            const int*   __restrict__ idx3, const float* __restrict__ c3,
                            const int*   __restrict__ idx4, const float* __restrict__ c4,
                            const int*   __restrict__ idx5, const float* __restrict__ c5)
{
    int t = blockIdx.x * blockDim.x + threadIdx.x;
    if (t < NTRI) {
        int rem = t, i = 0;
        while (rem >= 63 - i) { rem -= 63 - i; ++i; }
        int j = i + 1 + rem;
        g_tri[t] = b[i * 64 + j];
    }
    if (t < NM3) {
        unsigned p = (unsigned)idx3[t*3+0] | ((unsigned)idx3[t*3+1] << 8)
                   | ((unsigned)idx3[t*3+2] << 16);
        uint2 r; r.x = p; r.y = __float_as_uint(c3[t]);
        g_rec3[t] = r;
    }
    if (t < NM4) {
        unsigned p = (unsigned)idx4[t*4+0] | ((unsigned)idx4[t*4+1] << 8)
                   | ((unsigned)idx4[t*4+2] << 16) | ((unsigned)idx4[t*4+3] << 24);
        uint2 r; r.x = p; r.y = __float_as_uint(c4[t]);
        g_rec4[t] = r;
    }
    if (t < NM5) {
        unsigned p = (unsigned)idx5[t*5+0] | ((unsigned)idx5[t*5+1] << 8)
                   | ((unsigned)idx5[t*5+2] << 16) | ((unsigned)idx5[t*5+3] << 24);
        uint4 r; r.x = p; r.y = (unsigned)idx5[t*5+4];
        r.z = __float_as_uint(c5[t]); r.w = 0u;
        g_rec5[t] = r;
    }
    if (t < KC) {
        g_a[t]    = a[t];
        g_xoff[t] = (unsigned)S[t];
    }
}

// -------- kernel 1: gather + linear + quadratic; spill fp16 tile ------------
__global__ __launch_bounds__(TPB)
void quad_kernel(const float* __restrict__ x, float* __restrict__ out)
{
    __shared__ float    s_tri[NTRI];     // 8064 B
    __shared__ float    s_a[KC];
    __shared__ unsigned s_xi[KC];

    const int tid = threadIdx.x;

    {
        const float4* ts = (const float4*)g_tri;
        float4*       td = (float4*)s_tri;
        #pragma unroll 1
        for (int i = tid; i < NTRI/4; i += TPB) td[i] = ts[i];
        if (tid < KC) { s_a[tid] = g_a[tid]; s_xi[tid] = g_xoff[tid]; }
    }
    __syncthreads();

    const long long row = (long long)blockIdx.x * TPB + tid;
    const float* xr = x + row * DCOL;
    float xv[KC];
    #pragma unroll
    for (int k = 0; k < KC; ++k) xv[k] = __ldg(xr + s_xi[k]);

    // spill fp16 tile: [tile=blockIdx.x][col k][row tid], coalesced 2B stores
    {
        __half* xt = g_xs + (size_t)blockIdx.x * (KC * TROWS);
        #pragma unroll
        for (int k = 0; k < KC; ++k) xt[k * TROWS + tid] = __float2half(xv[k]);
    }

    float a0 = 0.f;
    #pragma unroll
    for (int k = 0; k < KC; ++k) a0 = fmaf(s_a[k], xv[k], a0);

    // quadratic form: fully unrolled triangular loop, broadcast LDS.128 coeffs
    {
        const float4* tri4 = (const float4*)s_tri;
        float4 tb = make_float4(0.f, 0.f, 0.f, 0.f);
        int p = 0;
        #pragma unroll
        for (int i = 0; i < KC - 1; ++i) {
            float s = 0.f;
            #pragma unroll
            for (int j = i + 1; j < KC; ++j) {
                if ((p & 3) == 0) tb = tri4[p >> 2];
                float bv = ((p & 3) == 0) ? tb.x :
                           ((p & 3) == 1) ? tb.y :
                           ((p & 3) == 2) ? tb.z : tb.w;
                s = fmaf(bv, xv[j], s);
                ++p;
            }
            a0 = fmaf(s, xv[i], a0);
        }
    }
    out[row] = a0;
}

__device__ __forceinline__ __half2 as_h2(unsigned u) {
    __half2 h;
    *reinterpret_cast<unsigned*>(&h) = u;
    return h;
}

// -------- kernel 2: monomials; 4 CTAs per tile (term quarters) --------------
__global__ __launch_bounds__(TPB)
void mono_kernel(float* __restrict__ out)
{
    __shared__ __half s_x[KC][TROWS];    // 16 KB, row stride 256B
    __shared__ float  s_redf[4][TROWS];  // 2 KB

    const int tid  = threadIdx.x;
    const int tile = blockIdx.x >> 2;
    const int par  = blockIdx.x & 3;

    // coalesced tile load: 16 KB = 1024 uint4 (L2-resident, just written)
    {
        const uint4* src = (const uint4*)(g_xs + (size_t)tile * (KC * TROWS));
        uint4*       dst = (uint4*)&s_x[0][0];
        #pragma unroll
        for (int i = 0; i < 8; ++i) dst[tid + i * TPB] = __ldg(src + tid + i * TPB);
    }
    __syncthreads();

    // 32 four-row groups x 4 warp slices (conflict-free LDS.64)
    const int g = tid & 31;             // group id: rows 4g..4g+3
    const int q = tid >> 5;             // warp slice 0..3
    const char* xb = (const char*)(&s_x[0][0]) + 8 * g;  // operand offset = idx<<8
    const int base = par * NMQ;         // this CTA's term quarter
    float m0 = 0.f, m1 = 0.f, m2 = 0.f, m3 = 0.f;

    {
        const int lo = base + q * (NMQ / 4), hi = lo + (NMQ / 4);
        #pragma unroll 4
        for (int t3 = lo; t3 < hi; ++t3) {
            uint2 r = __ldg(&g_rec3[t3]);
            unsigned o0 = (r.x << 8) & 0xFF00u;
            unsigned o1 =  r.x       & 0xFF00u;
            unsigned o2 = (r.x >> 8) & 0xFF00u;
            uint2 u0 = *(const uint2*)(xb + o0);
            uint2 u1 = *(const uint2*)(xb + o1);
            uint2 u2 = *(const uint2*)(xb + o2);
            __half2 pa = __hmul2(__hmul2(as_h2(u0.x), as_h2(u1.x)), as_h2(u2.x));
            __half2 pb = __hmul2(__hmul2(as_h2(u0.y), as_h2(u1.y)), as_h2(u2.y));
            float2 fa = __half22float2(pa);
            float2 fb = __half22float2(pb);
            float c = __uint_as_float(r.y);
            m0 = fmaf(c, fa.x, m0);
            m1 = fmaf(c, fa.y, m1);
            m2 = fmaf(c, fb.x, m2);
            m3 = fmaf(c, fb.y, m3);
        }
    }
    {
        const int lo = base + q * (NMQ / 4), hi = lo + (NMQ / 4);
        #pragma unroll 4
        for (int t4 = lo; t4 < hi; ++t4) {
            uint2 r = __ldg(&g_rec4[t4]);
            unsigned o0 = (r.x << 8)  & 0xFF00u;
            unsigned o1 =  r.x        & 0xFF00u;
            unsigned o2 = (r.x >> 8)  & 0xFF00u;
            unsigned o3 = (r.x >> 16) & 0xFF00u;
            uint2 u0 = *(const uint2*)(xb + o0);
            uint2 u1 = *(const uint2*)(xb + o1);
            uint2 u2 = *(const uint2*)(xb + o2);
            uint2 u3 = *(const uint2*)(xb + o3);
            __half2 pa = __hmul2(__hmul2(as_h2(u0.x), as_h2(u1.x)),
                                 __hmul2(as_h2(u2.x), as_h2(u3.x)));
            __half2 pb = __hmul2(__hmul2(as_h2(u0.y), as_h2(u1.y)),
                                 __hmul2(as_h2(u2.y), as_h2(u3.y)));
            float2 fa = __half22float2(pa);
            float2 fb = __half22float2(pb);
            float c = __uint_as_float(r.y);
            m0 = fmaf(c, fa.x, m0);
            m1 = fmaf(c, fa.y, m1);
            m2 = fmaf(c, fb.x, m2);
            m3 = fmaf(c, fb.y, m3);
        }
    }
    {
        const int lo = base + q * (NMQ / 4), hi = lo + (NMQ / 4);
        #pragma unroll 4
        for (int t5 = lo; t5 < hi; ++t5) {
            uint4 r = __ldg(&g_rec5[t5]);
            unsigned o0 = (r.x << 8)  & 0xFF00u;
            unsigned o1 =  r.x        & 0xFF00u;
            unsigned o2 = (r.x >> 8)  & 0xFF00u;
            unsigned o3 = (r.x >> 16) & 0xFF00u;
            unsigned o4 =  r.y << 8;
            uint2 u0 = *(const uint2*)(xb + o0);
            uint2 u1 = *(const uint2*)(xb + o1);
            uint2 u2 = *(const uint2*)(xb + o2);
            uint2 u3 = *(const uint2*)(xb + o3);
            uint2 u4 = *(const uint2*)(xb + o4);
            __half2 pa = __hmul2(__hmul2(__hmul2(as_h2(u0.x), as_h2(u1.x)),
                                         __hmul2(as_h2(u2.x), as_h2(u3.x))),
                                 as_h2(u4.x));
            __half2 pb = __hmul2(__hmul2(__hmul2(as_h2(u0.y), as_h2(u1.y)),
                                         __hmul2(as_h2(u2.y), as_h2(u3.y))),
                                 as_h2(u4.y));
            float2 fa = __half22float2(pa);
            float2 fb = __half22float2(pb);
            float c = __uint_as_float(r.z);
            m0 = fmaf(c, fa.x, m0);
            m1 = fmaf(c, fa.y, m1);
            m2 = fmaf(c, fb.x, m2);
            m3 = fmaf(c, fb.y, m3);
        }
    }

    *(float4*)&s_redf[q][4 * g] = make_float4(m0, m1, m2, m3);
    __syncthreads();

    // one thread per row: combine this CTA's 4 slices, accumulate to out
    {
        float r = s_redf[0][tid] + s_redf[1][tid] + s_redf[2][tid] + s_redf[3][tid];
        atomicAdd(out + (size_t)tile * TROWS + tid, r);
    }
}

// -------- launch --------
extern "C" void kernel_launch(void* const* d_in, const int* in_sizes, int n_in,
                              void* d_out, int out_size)
{
    const float* x    = (const float*)d_in[0];
    const int*   S    = (const int*)  d_in[1];
    const float* a    = (const float*)d_in[2];
    const float* b    = (const float*)d_in[3];
    const int*   idx3 = (const int*)  d_in[4];
    const float* c3   = (const float*)d_in[5];
    const int*   idx4 = (const int*)  d_in[6];
    const float* c4   = (const float*)d_in[7];
    const int*   idx5 = (const int*)  d_in[8];
    const float* c5   = (const float*)d_in[9];
    float* out = (float*)d_out;

    prep_kernel<<<32, 128>>>(b, S, a, idx3, c3, idx4, c4, idx5, c5);
    quad_kernel<<<NTILES, TPB>>>(x, out);            // out = lin+quad, spills fp16 tiles
    mono_kernel<<<NTILES * NSPLIT, TPB>>>(out);      // += monomials (4 quarters per tile)
}